// round 17
// baseline (speedup 1.0000x reference)
#include <cuda_runtime.h>
#include <math.h>

#define BATCH 4
#define TQL   128
#define TKL   512
#define ND    512
#define OD    512
#define MROWS (BATCH * TQL)     // 512
#define SLAB  (MROWS * 512)     // one partial slab

// Scratch (device globals -- no allocation allowed)
__device__ __align__(16) float g_scores[MROWS * TKL];   // exp(score) (unnormalized)
__device__ __align__(16) float g_ssum  [MROWS * 2];     // per-row half-sums of exp
__device__ __align__(16) float g_part  [4 * SLAB];      // attq partials, then ctx partials
__device__ __align__(16) float g_part2 [6 * SLAB];      // out-GEMM partials (qhalf 0-1, chalf 2-5)

__device__ __forceinline__ float fast_tanh(float x) {
    float y;
    asm("tanh.approx.f32 %0, %1;" : "=f"(y) : "f"(x));
    return y;
}

// ----------------------------------------------------------------------------
// Split-K NT GEMM body over a K=512 range:
//   part[z0+bz][m][n] = sum_{k in chunk bz} A0[m,k] * B[n, boff+k]
// 64x64 tile, BK=16, 256 threads, 4x4 micro-tile, double-buffered smem.
// ----------------------------------------------------------------------------
template <int SPLITS>
__device__ __forceinline__ void gemm_body(
    const float* __restrict__ A0, const float* __restrict__ B,
    int bstride, int boff, float* __restrict__ part, int z0,
    int bx, int by, int bz)
{
    constexpr int CHUNK  = 512 / SPLITS;
    constexpr int STAGES = CHUNK / 16;

    __shared__ float As[2][16][68];
    __shared__ float Bs[2][16][68];

    const int tid = threadIdx.x;
    const int r   = tid >> 2;
    const int c   = tid & 3;
    const int ty  = tid >> 4;
    const int tx  = tid & 15;
    const int m0  = by * 64;
    const int n0  = bx * 64;
    const int kst = bz * CHUNK;

    float acc[4][4] = {};

    {
        float4 av = *(const float4*)(A0 + (size_t)(m0 + r) * 512 + kst + 4 * c);
        float4 bv = *(const float4*)(B + (size_t)(n0 + r) * bstride + boff + kst + 4 * c);
        float a4[4] = {av.x, av.y, av.z, av.w};
        float b4[4] = {bv.x, bv.y, bv.z, bv.w};
#pragma unroll
        for (int j = 0; j < 4; j++) {
            As[0][4 * c + j][r] = a4[j];
            Bs[0][4 * c + j][r] = b4[j];
        }
    }
    __syncthreads();

    int buf = 0;
#pragma unroll 1
    for (int s = 0; s < STAGES; s++) {
        float4 anx, bnx;
        if (s + 1 < STAGES) {
            const int kb = kst + (s + 1) * 16;
            anx = *(const float4*)(A0 + (size_t)(m0 + r) * 512 + kb + 4 * c);
            bnx = *(const float4*)(B + (size_t)(n0 + r) * bstride + boff + kb + 4 * c);
        }

#pragma unroll
        for (int kk = 0; kk < 16; kk++) {
            float4 a = *(const float4*)&As[buf][kk][ty * 4];
            float4 b = *(const float4*)&Bs[buf][kk][tx * 4];
            float a4[4] = {a.x, a.y, a.z, a.w};
            float b4[4] = {b.x, b.y, b.z, b.w};
#pragma unroll
            for (int i = 0; i < 4; i++)
#pragma unroll
                for (int j = 0; j < 4; j++)
                    acc[i][j] += a4[i] * b4[j];
        }

        if (s + 1 < STAGES) {
            const int nb = buf ^ 1;
            float a4[4] = {anx.x, anx.y, anx.z, anx.w};
            float b4[4] = {bnx.x, bnx.y, bnx.z, bnx.w};
#pragma unroll
            for (int j = 0; j < 4; j++) {
                As[nb][4 * c + j][r] = a4[j];
                Bs[nb][4 * c + j][r] = b4[j];
            }
            __syncthreads();
            buf = nb;
        }
    }

    float* pp = part + (size_t)(z0 + bz) * SLAB;
#pragma unroll
    for (int i = 0; i < 4; i++) {
        float4 v = make_float4(acc[i][0], acc[i][1], acc[i][2], acc[i][3]);
        *(float4*)&pp[(size_t)(m0 + ty * 4 + i) * 512 + n0 + tx * 4] = v;
    }
}

// ----------------------------------------------------------------------------
// Scores body (4 queries x 256 keys per block) with fused attq reduce (4
// slabs) and max-free exp: writes exp(score) to g_scores and per-row-half
// sums to g_ssum. (Scores bounded by sum|w_att| ~ 8.3 -> exp is fp32-safe.)
// ----------------------------------------------------------------------------
__device__ __forceinline__ void scores_body(
    const float* __restrict__ keys,
    const float* __restrict__ w_att,
    const float* __restrict__ b_att,
    const float* __restrict__ b_q,
    int bi)
{
    __shared__ float s_aq[4][512];   // 8 KB
    __shared__ float s_sc[4][256];   // 4 KB (exp scores, this key-half)

    const int tid  = threadIdx.x;
    const int wid  = tid >> 5;
    const int lane = tid & 31;
    const int kh   = bi & 1;
    const int q0   = ((bi >> 1) & 31) << 2;
    const int b    = bi >> 6;

    // 1) fused split-K reduce of att_query (4 slabs, vectorized)
#pragma unroll
    for (int e = 0; e < 2; e++) {
        const int f  = tid + 256 * e;      // float4 index 0..511
        const int q  = f >> 7, ng = f & 127;
        const size_t row4 = ((size_t)(b * TQL + q0 + q) * 512) / 4 + ng;
        float4 s = ((const float4*)b_q)[ng];
#pragma unroll
        for (int sp = 0; sp < 4; sp++) {
            float4 t = ((const float4*)g_part)[(size_t)sp * (SLAB / 4) + row4];
            s.x += t.x; s.y += t.y; s.z += t.z; s.w += t.w;
        }
        *(float4*)&s_aq[q][ng * 4] = s;
    }
    __syncthreads();

    // 2) register-resident w_att + att_query (lane owns 16 n-positions)
    float wreg[16];
    float areg[4][16];
#pragma unroll
    for (int i = 0; i < 4; i++) {
        float4 w4 = *(const float4*)(w_att + i * 128 + lane * 4);
        wreg[i * 4 + 0] = w4.x; wreg[i * 4 + 1] = w4.y;
        wreg[i * 4 + 2] = w4.z; wreg[i * 4 + 3] = w4.w;
#pragma unroll
        for (int q = 0; q < 4; q++) {
            float4 a4 = *(const float4*)&s_aq[q][i * 128 + lane * 4];
            areg[q][i * 4 + 0] = a4.x; areg[q][i * 4 + 1] = a4.y;
            areg[q][i * 4 + 2] = a4.z; areg[q][i * 4 + 3] = a4.w;
        }
    }
    const float batt = b_att[0];
    const float* keyb = keys + (size_t)b * TKL * ND;
    float* sco = g_scores + (size_t)(b * TQL + q0) * TKL;

    // 3) scores + exp (MUFU tanh bound)
    const int kend = kh * 256 + 256;
    for (int k = kh * 256 + wid; k < kend; k += 8) {
        const float* kr = keyb + (size_t)k * ND;
        float acc0 = 0.f, acc1 = 0.f, acc2 = 0.f, acc3 = 0.f;
#pragma unroll
        for (int i = 0; i < 4; i++) {
            float4 k4 = *(const float4*)(kr + i * 128 + lane * 4);
            float kv[4] = {k4.x, k4.y, k4.z, k4.w};
#pragma unroll
            for (int j = 0; j < 4; j++) {
                const float w = wreg[i * 4 + j];
                acc0 += w * fast_tanh(areg[0][i * 4 + j] + kv[j]);
                acc1 += w * fast_tanh(areg[1][i * 4 + j] + kv[j]);
                acc2 += w * fast_tanh(areg[2][i * 4 + j] + kv[j]);
                acc3 += w * fast_tanh(areg[3][i * 4 + j] + kv[j]);
            }
        }
#pragma unroll
        for (int off = 16; off; off >>= 1) {
            acc0 += __shfl_xor_sync(0xffffffffu, acc0, off);
            acc1 += __shfl_xor_sync(0xffffffffu, acc1, off);
            acc2 += __shfl_xor_sync(0xffffffffu, acc2, off);
            acc3 += __shfl_xor_sync(0xffffffffu, acc3, off);
        }
        if (lane == 0) {
            const int kl = k - kh * 256;
            float e0 = __expf(acc0 + batt);
            float e1 = __expf(acc1 + batt);
            float e2 = __expf(acc2 + batt);
            float e3 = __expf(acc3 + batt);
            s_sc[0][kl] = e0; sco[0 * TKL + k] = e0;
            s_sc[1][kl] = e1; sco[1 * TKL + k] = e1;
            s_sc[2][kl] = e2; sco[2 * TKL + k] = e2;
            s_sc[3][kl] = e3; sco[3 * TKL + k] = e3;
        }
    }
    __syncthreads();

    // 4) per-row-half exp sums (warps 0-3, one row each)
    if (wid < 4) {
        float s = 0.f;
#pragma unroll
        for (int i = 0; i < 8; i++) s += s_sc[wid][lane + 32 * i];
#pragma unroll
        for (int off = 16; off; off >>= 1) s += __shfl_xor_sync(0xffffffffu, s, off);
        if (lane == 0)
            g_ssum[(size_t)(b * TQL + q0 + wid) * 2 + kh] = s;
    }
}

// ----------------------------------------------------------------------------
// MEGA: blocks [0,256) = scores+exp (MUFU-bound);
//       blocks [256,384) = out-GEMM query-half, splits=2 (FFMA, hidden).
// ----------------------------------------------------------------------------
__global__ __launch_bounds__(256) void mega_scores_qgemm(
    const float* __restrict__ keys,
    const float* __restrict__ w_att,
    const float* __restrict__ b_att,
    const float* __restrict__ b_q,
    const float* __restrict__ query,
    const float* __restrict__ W_out)
{
    if (blockIdx.x < 256) {
        scores_body(keys, w_att, b_att, b_q, blockIdx.x);
    } else {
        const int g = blockIdx.x - 256;      // 128 = 8n x 8m x 2z
        gemm_body<2>(query, W_out, 1024, 0, g_part2, 0,
                     g & 7, (g >> 3) & 7, g >> 6);
    }
}

// ----------------------------------------------------------------------------
// attq GEMM (splits = 4, grid 8x8x4 = 256, 3 CTAs/SM)
// ----------------------------------------------------------------------------
__global__ __launch_bounds__(256, 3) void gemm_attq(
    const float* __restrict__ query, const float* __restrict__ W_q)
{
    gemm_body<4>(query, W_q, 512, 0, g_part, 0, blockIdx.x, blockIdx.y, blockIdx.z);
}

// ----------------------------------------------------------------------------
// Out-GEMM ctx-half with FUSED ctx-slab reduction:
//   A[m,k] = sum_{sp<4} ctx_part[sp][m][k]   (summed at tile load)
// B = W_out[:, 512:1024]. Writes partials to g_part2 slabs 2..5.
// maxBlocks=2 to leave register headroom for the 4-slab load (R13 lesson).
// ----------------------------------------------------------------------------
__global__ __launch_bounds__(256, 2) void gemm_out_chalf_fused(
    const float* __restrict__ W_out)
{
    constexpr int CHUNK  = 128;   // splits = 4
    constexpr int STAGES = CHUNK / 16;

    __shared__ float As[2][16][68];
    __shared__ float Bs[2][16][68];

    const int tid = threadIdx.x;
    const int r   = tid >> 2;
    const int c   = tid & 3;
    const int ty  = tid >> 4;
    const int tx  = tid & 15;
    const int m0  = blockIdx.y * 64;
    const int n0  = blockIdx.x * 64;
    const int kst = blockIdx.z * CHUNK;

    const size_t arow = (size_t)(m0 + r) * 512;

    auto load_a = [&](int kb) -> float4 {
        const float* p0 = g_part + arow + kb + 4 * c;
        float4 s = *(const float4*)p0;
        float4 t1 = *(const float4*)(p0 + SLAB);
        s.x += t1.x; s.y += t1.y; s.z += t1.z; s.w += t1.w;
        float4 t2 = *(const float4*)(p0 + 2 * SLAB);
        s.x += t2.x; s.y += t2.y; s.z += t2.z; s.w += t2.w;
        float4 t3 = *(const float4*)(p0 + 3 * SLAB);
        s.x += t3.x; s.y += t3.y; s.z += t3.z; s.w += t3.w;
        return s;
    };

    float acc[4][4] = {};

    {
        float4 av = load_a(kst);
        float4 bv = *(const float4*)(W_out + (size_t)(n0 + r) * 1024 + 512 + kst + 4 * c);
        float a4[4] = {av.x, av.y, av.z, av.w};
        float b4[4] = {bv.x, bv.y, bv.z, bv.w};
#pragma unroll
        for (int j = 0; j < 4; j++) {
            As[0][4 * c + j][r] = a4[j];
            Bs[0][4 * c + j][r] = b4[j];
        }
    }
    __syncthreads();

    int buf = 0;
#pragma unroll 1
    for (int s = 0; s < STAGES; s++) {
        float4 anx, bnx;
        if (s + 1 < STAGES) {
            const int kb = kst + (s + 1) * 16;
            anx = load_a(kb);
            bnx = *(const float4*)(W_out + (size_t)(n0 + r) * 1024 + 512 + kb + 4 * c);
        }

#pragma unroll
        for (int kk = 0; kk < 16; kk++) {
            float4 a = *(const float4*)&As[buf][kk][ty * 4];
            float4 b = *(const float4*)&Bs[buf][kk][tx * 4];
            float a4[4] = {a.x, a.y, a.z, a.w};
            float b4[4] = {b.x, b.y, b.z, b.w};
#pragma unroll
            for (int i = 0; i < 4; i++)
#pragma unroll
                for (int j = 0; j < 4; j++)
                    acc[i][j] += a4[i] * b4[j];
        }

        if (s + 1 < STAGES) {
            const int nb = buf ^ 1;
            float a4[4] = {anx.x, anx.y, anx.z, anx.w};
            float b4[4] = {bnx.x, bnx.y, bnx.z, bnx.w};
#pragma unroll
            for (int j = 0; j < 4; j++) {
                As[nb][4 * c + j][r] = a4[j];
                Bs[nb][4 * c + j][r] = b4[j];
            }
            __syncthreads();
            buf = nb;
        }
    }

    float* pp = g_part2 + (size_t)(2 + blockIdx.z) * SLAB;
#pragma unroll
    for (int i = 0; i < 4; i++) {
        float4 v = make_float4(acc[i][0], acc[i][1], acc[i][2], acc[i][3]);
        *(float4*)&pp[(size_t)(m0 + ty * 4 + i) * 512 + n0 + tx * 4] = v;
    }
}

// ----------------------------------------------------------------------------
// Split-K NN GEMM for context with FUSED softmax normalization (splits=4):
//   part[z][m][n] = sum_k (exp_sc[m,k] / rowsum[m]) * V_b[k,n]
// A-tiles are scaled by 1/rowsum at load; bx==0 blocks also write probs.
// ----------------------------------------------------------------------------
template <int SPLITS>
__global__ __launch_bounds__(256, 3) void gemm_ctx_splitk(
    const float* __restrict__ values,
    float* __restrict__ probs)
{
    constexpr int CHUNK  = TKL / SPLITS;
    constexpr int STAGES = CHUNK / 16;

    __shared__ float As[2][16][68];
    __shared__ float Bs[2][16][68];

    const int tid = threadIdx.x;
    const int r   = tid >> 2;
    const int c   = tid & 3;
    const int bk  = tid >> 4;
    const int bn  = (tid & 15) * 4;
    const int ty  = tid >> 4;
    const int tx  = tid & 15;
    const int m0  = blockIdx.y * 64;
    const int n0  = blockIdx.x * 64;
    const int kst = blockIdx.z * CHUNK;
    const bool wp = (blockIdx.x == 0);

    const float* valb = values + (size_t)(m0 >> 7) * TKL * ND;
    const float* P = g_scores;

    const int mrow = m0 + r;
    const float inv = 1.0f / (g_ssum[2 * mrow] + g_ssum[2 * mrow + 1]);

    float acc[4][4] = {};

    {
        float4 av = *(const float4*)(P + (size_t)mrow * TKL + kst + 4 * c);
        float4 bvv = *(const float4*)(valb + (size_t)(kst + bk) * ND + n0 + bn);
        float a4[4] = {av.x * inv, av.y * inv, av.z * inv, av.w * inv};
#pragma unroll
        for (int j = 0; j < 4; j++) As[0][4 * c + j][r] = a4[j];
        if (wp)
            *(float4*)(probs + (size_t)mrow * TKL + kst + 4 * c) =
                make_float4(a4[0], a4[1], a4[2], a4[3]);
        *(float4*)&Bs[0][bk][bn] = bvv;
    }
    __syncthreads();

    int buf = 0;
#pragma unroll 1
    for (int s = 0; s < STAGES; s++) {
        float4 anx, bnx;
        if (s + 1 < STAGES) {
            const int kb = kst + (s + 1) * 16;
            anx = *(const float4*)(P + (size_t)mrow * TKL + kb + 4 * c);
            bnx = *(const float4*)(valb + (size_t)(kb + bk) * ND + n0 + bn);
        }

#pragma unroll
        for (int kk = 0; kk < 16; kk++) {
            float4 a = *(const float4*)&As[buf][kk][ty * 4];
            float4 b = *(const float4*)&Bs[buf][kk][tx * 4];
            float a4[4] = {a.x, a.y, a.z, a.w};
            float b4[4] = {b.x, b.y, b.z, b.w};
#pragma unroll
            for (int i = 0; i < 4; i++)
#pragma unroll
                for (int j = 0; j < 4; j++)
                    acc[i][j] += a4[i] * b4[j];
        }

        if (s + 1 < STAGES) {
            const int nb = buf ^ 1;
            const int kb = kst + (s + 1) * 16;
            float a4[4] = {anx.x * inv, anx.y * inv, anx.z * inv, anx.w * inv};
#pragma unroll
            for (int j = 0; j < 4; j++) As[nb][4 * c + j][r] = a4[j];
            if (wp)
                *(float4*)(probs + (size_t)mrow * TKL + kb + 4 * c) =
                    make_float4(a4[0], a4[1], a4[2], a4[3]);
            *(float4*)&Bs[nb][bk][bn] = bnx;
            __syncthreads();
            buf = nb;
        }
    }

    float* pp = g_part + (size_t)blockIdx.z * SLAB;
#pragma unroll
    for (int i = 0; i < 4; i++) {
        float4 v = make_float4(acc[i][0], acc[i][1], acc[i][2], acc[i][3]);
        *(float4*)&pp[(size_t)(m0 + ty * 4 + i) * 512 + n0 + tx * 4] = v;
    }
}

// ----------------------------------------------------------------------------
// Final reduction: 6 slabs of g_part2 + b_out, tanh -> out
// ----------------------------------------------------------------------------
__global__ __launch_bounds__(256) void reduce_out_k(
    const float* __restrict__ bias, float* __restrict__ dext)
{
    const int idx = blockIdx.x * 256 + threadIdx.x;
    const float4* p = (const float4*)g_part2;
    float4 s = p[idx];
#pragma unroll
    for (int sp = 1; sp < 6; sp++) {
        float4 t = p[(size_t)sp * (SLAB / 4) + idx];
        s.x += t.x; s.y += t.y; s.z += t.z; s.w += t.w;
    }
    const float4 bb = ((const float4*)bias)[idx & (512 / 4 - 1)];
    s.x = tanhf(s.x + bb.x); s.y = tanhf(s.y + bb.y);
    s.z = tanhf(s.z + bb.z); s.w = tanhf(s.w + bb.w);
    ((float4*)dext)[idx] = s;
}

// ----------------------------------------------------------------------------
// Launch sequence (graph-capturable, allocation-free):
//   1) gemm_attq:  query @ W_q^T partials (4 slabs)      -> g_part[0..3]
//   2) MEGA:       scores + exp + row-half sums          -> g_scores, g_ssum
//                  || out-GEMM query-half (2 slabs)      -> g_part2[0..1]
//   3) gemm_ctx:   (exp/rowsum) @ values (4 slabs)       -> g_part[0..3]
//                  (bx==0 blocks also emit probs output)
//   4) chalf FUSED: sum 4 ctx slabs at A-load, GEMM      -> g_part2[2..5]
//   5) reduce_out: 6 slabs + b_out + tanh                -> out (output)
// ----------------------------------------------------------------------------
extern "C" void kernel_launch(void* const* d_in, const int* in_sizes, int n_in,
                              void* d_out, int out_size)
{
    const float* query  = (const float*)d_in[0];
    const float* keys   = (const float*)d_in[1];
    const float* values = (const float*)d_in[2];
    const float* W_q    = (const float*)d_in[3];
    const float* b_q    = (const float*)d_in[4];
    const float* w_att  = (const float*)d_in[5];
    const float* b_att  = (const float*)d_in[6];
    const float* W_out  = (const float*)d_in[7];
    const float* b_out  = (const float*)d_in[8];

    float* out   = (float*)d_out;
    float* probs = out + (size_t)MROWS * OD;

    gemm_attq<<<dim3(8, 8, 4), 256>>>(query, W_q);

    mega_scores_qgemm<<<384, 256>>>(keys, w_att, b_att, b_q, query, W_out);

    gemm_ctx_splitk<4><<<dim3(8, 8, 4), 256>>>(values, probs);

    gemm_out_chalf_fused<<<dim3(8, 8, 4), 256>>>(W_out);

    reduce_out_k<<<256, 256>>>(b_out, out);
}